// round 2
// baseline (speedup 1.0000x reference)
#include <cuda_runtime.h>
#include <math.h>

#define N_NODES 4096
#define F_IN    1386
#define NHID    1024
#define NHEADS  8
#define CODE    64
#define KMAX    64
#define LRELU_A 0.2f

// ---------------- scratch (allocation-free: __device__ globals) ----------------
__device__ float         g_xn  [(long long)N_NODES * F_IN];            // 22.7 MB
__device__ unsigned char g_flags[(long long)N_NODES * N_NODES];        // 16.8 MB
__device__ int           g_nbr [N_NODES * KMAX];
__device__ int           g_cnt [N_NODES];
__device__ float         g_Wh  [(long long)NHEADS * N_NODES * NHID];   // 134 MB
__device__ float         g_f1  [NHEADS * N_NODES];
__device__ float         g_f2  [NHEADS * N_NODES];
__device__ float         g_hcat[(long long)N_NODES * NHEADS * NHID];   // 134 MB
__device__ float         g_out1[N_NODES * CODE];
__device__ float         g_f1o [N_NODES];
__device__ float         g_f2o [N_NODES];

// ---------------- generic 128x128x8 FFMA GEMM body ----------------
#define BM 128
#define BN 128
#define BK 8

template<bool TRANSB, bool FLAGS>
__device__ __forceinline__ void gemm_body(const float* __restrict__ A,
                                          const float* __restrict__ B,
                                          float* __restrict__ C,
                                          unsigned char* __restrict__ CF,
                                          int M, int N, int K)
{
    __shared__ float As[BK][BM];
    __shared__ float Bs[BK][BN];

    const int bm = blockIdx.y * BM;
    const int bn = blockIdx.x * BN;
    const int tid = threadIdx.x;          // 256 threads
    const int tx = tid & 15;              // 0..15  -> 8 cols each
    const int ty = tid >> 4;              // 0..15  -> 8 rows each

    float acc[8][8];
    #pragma unroll
    for (int i = 0; i < 8; i++)
        #pragma unroll
        for (int j = 0; j < 8; j++) acc[i][j] = 0.f;

    for (int k0 = 0; k0 < K; k0 += BK) {
        // load A tile: [BM][BK], k fastest per thread (4 elems)
        #pragma unroll
        for (int l = 0; l < 4; l++) {
            int idx = tid * 4 + l;            // over [m][k]
            int m = idx >> 3, kk = idx & 7;
            int gm = bm + m, gk = k0 + kk;
            As[kk][m] = (gm < M && gk < K) ? A[(long long)gm * K + gk] : 0.f;
        }
        // load B tile
        #pragma unroll
        for (int l = 0; l < 4; l++) {
            int idx = tid * 4 + l;
            if (!TRANSB) {
                int kk = idx >> 7, n = idx & 127;   // n fastest, coalesced
                int gk = k0 + kk, gn = bn + n;
                Bs[kk][n] = (gk < K && gn < N) ? B[(long long)gk * N + gn] : 0.f;
            } else {
                int n = idx >> 3, kk = idx & 7;     // B is N x K row-major
                int gk = k0 + kk, gn = bn + n;
                Bs[kk][n] = (gk < K && gn < N) ? B[(long long)gn * K + gk] : 0.f;
            }
        }
        __syncthreads();

        #pragma unroll
        for (int kk = 0; kk < BK; kk++) {
            float ra[8], rb[8];
            #pragma unroll
            for (int i = 0; i < 8; i++) ra[i] = As[kk][ty * 8 + i];
            #pragma unroll
            for (int j = 0; j < 8; j++) rb[j] = Bs[kk][tx * 8 + j];
            #pragma unroll
            for (int i = 0; i < 8; i++)
                #pragma unroll
                for (int j = 0; j < 8; j++)
                    acc[i][j] = fmaf(ra[i], rb[j], acc[i][j]);
        }
        __syncthreads();
    }

    #pragma unroll
    for (int i = 0; i < 8; i++) {
        int gm = bm + ty * 8 + i;
        if (gm >= M) continue;
        #pragma unroll
        for (int j = 0; j < 8; j++) {
            int gn = bn + tx * 8 + j;
            if (gn >= N) continue;
            if (FLAGS) CF[(long long)gm * N + gn] = (acc[i][j] >= 0.8f) ? 1 : 0;
            else       C [(long long)gm * N + gn] = acc[i][j];
        }
    }
}

// ---------------- kernels ----------------

// row L2-normalize x -> g_xn
__global__ void k_normalize(const float* __restrict__ x)
{
    const int row = blockIdx.x;
    const int tid = threadIdx.x;
    __shared__ float red[256];
    const float* xr = x + (long long)row * F_IN;
    float s = 0.f;
    for (int c = tid; c < F_IN; c += 256) { float v = xr[c]; s += v * v; }
    red[tid] = s; __syncthreads();
    for (int off = 128; off > 0; off >>= 1) {
        if (tid < off) red[tid] += red[tid + off];
        __syncthreads();
    }
    __shared__ float s_norm;
    if (tid == 0) s_norm = fmaxf(sqrtf(red[0]), 1e-12f);
    __syncthreads();
    float inv = 1.f / s_norm;
    float* o = g_xn + (long long)row * F_IN;
    for (int c = tid; c < F_IN; c += 256) o[c] = xr[c] * inv;
}

// sim = xn @ xn^T, fused threshold -> flags
__global__ void k_sim()
{
    gemm_body<true, true>(g_xn, g_xn, nullptr, g_flags, N_NODES, N_NODES, F_IN);
}

// deterministic per-row neighbor lists (column order)
__global__ void k_build_nbr()
{
    int row = blockIdx.x * blockDim.x + threadIdx.x;
    if (row >= N_NODES) return;
    const unsigned char* fr = g_flags + (long long)row * N_NODES;
    int cnt = 0;
    for (int j8 = 0; j8 < N_NODES; j8 += 8) {
        unsigned long long w = *(const unsigned long long*)(fr + j8);
        if (w == 0ull) continue;
        #pragma unroll
        for (int b = 0; b < 8; b++) {
            if ((w >> (8 * b)) & 0xffull) {
                if (cnt < KMAX) g_nbr[row * KMAX + cnt] = j8 + b;
                cnt++;
            }
        }
    }
    g_cnt[row] = (cnt > KMAX) ? KMAX : cnt;
}

// batched Wh[h] = x @ W_att[h]
__global__ void k_Wh(const float* __restrict__ x, const float* __restrict__ W_att)
{
    const float* B = W_att + (long long)blockIdx.z * F_IN * NHID;
    float* C = g_Wh + (long long)blockIdx.z * N_NODES * NHID;
    gemm_body<false, false>(x, B, C, nullptr, N_NODES, NHID, F_IN);
}

// f1/f2 per (row, head)
__global__ void k_f12(const float* __restrict__ a_att)
{
    const int i = blockIdx.x, h = blockIdx.y, tid = threadIdx.x; // 128 threads
    const float* w = g_Wh + ((long long)h * N_NODES + i) * NHID;
    const float* a = a_att + (long long)h * 2 * NHID;
    float s1 = 0.f, s2 = 0.f;
    for (int c = tid; c < NHID; c += 128) {
        float v = w[c];
        s1 = fmaf(v, a[c], s1);
        s2 = fmaf(v, a[NHID + c], s2);
    }
    __shared__ float r1[128], r2[128];
    r1[tid] = s1; r2[tid] = s2; __syncthreads();
    for (int off = 64; off > 0; off >>= 1) {
        if (tid < off) { r1[tid] += r1[tid + off]; r2[tid] += r2[tid + off]; }
        __syncthreads();
    }
    if (tid == 0) { g_f1[h * N_NODES + i] = r1[0]; g_f2[h * N_NODES + i] = r2[0]; }
}

// per-(row, head) masked softmax + aggregate + ELU -> hcat
__global__ void k_head_attn()
{
    const int i = blockIdx.x, h = blockIdx.y, tid = threadIdx.x; // 256 threads
    __shared__ float w[KMAX];
    __shared__ int   nb[KMAX];
    __shared__ int   scnt;
    if (tid == 0) {
        int c = g_cnt[i]; scnt = c;
        float f1i = g_f1[h * N_NODES + i];
        float m = -INFINITY;
        for (int j = 0; j < c; j++) {
            int col = g_nbr[i * KMAX + j]; nb[j] = col;
            float v = f1i + g_f2[h * N_NODES + col];
            v = (v > 0.f) ? v : LRELU_A * v;
            w[j] = v; if (v > m) m = v;
        }
        float s = 0.f;
        for (int j = 0; j < c; j++) { float e = expf(w[j] - m); w[j] = e; s += e; }
        float inv = 1.f / s;
        for (int j = 0; j < c; j++) w[j] *= inv;
    }
    __syncthreads();
    const int c = scnt;
    for (int col = tid; col < NHID; col += 256) {
        float acc = 0.f;
        for (int j = 0; j < c; j++)
            acc = fmaf(w[j], g_Wh[((long long)h * N_NODES + nb[j]) * NHID + col], acc);
        acc = (acc > 0.f) ? acc : expm1f(acc);   // ELU (concat heads)
        g_hcat[(long long)i * (NHEADS * NHID) + h * NHID + col] = acc;
    }
}

// out1 = hcat @ W_out
__global__ void k_out(const float* __restrict__ W_out)
{
    gemm_body<false, false>(g_hcat, W_out, g_out1, nullptr, N_NODES, CODE, NHEADS * NHID);
}

// f1o/f2o per row
__global__ void k_f12o(const float* __restrict__ a_out)
{
    const int i = blockIdx.x, tid = threadIdx.x; // 64 threads
    float v = g_out1[i * CODE + tid];
    float s1 = v * a_out[tid];
    float s2 = v * a_out[CODE + tid];
    __shared__ float r1[64], r2[64];
    r1[tid] = s1; r2[tid] = s2; __syncthreads();
    for (int off = 32; off > 0; off >>= 1) {
        if (tid < off) { r1[tid] += r1[tid + off]; r2[tid] += r2[tid + off]; }
        __syncthreads();
    }
    if (tid == 0) { g_f1o[i] = r1[0]; g_f2o[i] = r2[0]; }
}

// final attention (no elu) + tanh -> d_out
__global__ void k_final(float* __restrict__ out)
{
    const int i = blockIdx.x, tid = threadIdx.x; // 64 threads
    __shared__ float w[KMAX];
    __shared__ int   nb[KMAX];
    __shared__ int   scnt;
    if (tid == 0) {
        int c = g_cnt[i]; scnt = c;
        float f1i = g_f1o[i];
        float m = -INFINITY;
        for (int j = 0; j < c; j++) {
            int col = g_nbr[i * KMAX + j]; nb[j] = col;
            float v = f1i + g_f2o[col];
            v = (v > 0.f) ? v : LRELU_A * v;
            w[j] = v; if (v > m) m = v;
        }
        float s = 0.f;
        for (int j = 0; j < c; j++) { float e = expf(w[j] - m); w[j] = e; s += e; }
        float inv = 1.f / s;
        for (int j = 0; j < c; j++) w[j] *= inv;
    }
    __syncthreads();
    const int c = scnt;
    float acc = 0.f;
    for (int j = 0; j < c; j++)
        acc = fmaf(w[j], g_out1[nb[j] * CODE + tid], acc);
    out[i * CODE + tid] = tanhf(acc);
}

// ---------------- launch ----------------
extern "C" void kernel_launch(void* const* d_in, const int* in_sizes, int n_in,
                              void* d_out, int out_size)
{
    const float* x     = (const float*)d_in[0];   // (4096, 1386)
    const float* W_att = (const float*)d_in[1];   // (8, 1386, 1024)
    const float* a_att = (const float*)d_in[2];   // (8, 2048, 1)
    const float* W_out = (const float*)d_in[3];   // (8192, 64)
    const float* a_out = (const float*)d_in[4];   // (128, 1)
    float* out = (float*)d_out;                   // (4096, 64)

    k_normalize<<<N_NODES, 256>>>(x);
    k_sim<<<dim3(N_NODES / BN, N_NODES / BM), 256>>>();
    k_build_nbr<<<N_NODES / 256, 256>>>();
    k_Wh<<<dim3(NHID / BN, N_NODES / BM, NHEADS), 256>>>(x, W_att);
    k_f12<<<dim3(N_NODES, NHEADS), 128>>>(a_att);
    k_head_attn<<<dim3(N_NODES, NHEADS), 256>>>();
    k_out<<<dim3(1, N_NODES / BM), 256>>>(W_out);
    k_f12o<<<N_NODES, 64>>>(a_out);
    k_final<<<N_NODES, 64>>>(out);
}

// round 9
// speedup vs baseline: 2.5521x; 2.5521x over previous
#include <cuda_runtime.h>
#include <math.h>
#include <stdint.h>

#define N_NODES 4096
#define F_IN    1386
#define NHID    1024
#define NHEADS  8
#define CODE    64
#define KMAX    64
#define LRELU_A 0.2f

// ---------------- scratch (allocation-free: __device__ globals) ----------------
__device__ float         g_xn  [(long long)N_NODES * F_IN];
__device__ unsigned char g_flags[(long long)N_NODES * N_NODES];
__device__ int           g_nbr [N_NODES * KMAX];
__device__ int           g_cnt [N_NODES];
__device__ float         g_Wh  [(long long)NHEADS * N_NODES * NHID];
__device__ float         g_f1  [NHEADS * N_NODES];
__device__ float         g_f2  [NHEADS * N_NODES];
__device__ float         g_hcat[(long long)N_NODES * NHEADS * NHID];
__device__ float         g_out1[N_NODES * CODE];
__device__ float         g_f1o [N_NODES];
__device__ float         g_f2o [N_NODES];

// ---------------- tf32 warp-MMA GEMM: 128x128x32 tile, 8 warps ----------------
#define TBM 128
#define TBN 128
#define TBK 32
#define AS_STRIDE 36    // %32==4 -> frag LDS conflict-free
#define BS_STRIDE 136   // %32==8 -> frag LDS conflict-free (136*4B = 544B, 16B-mult)

__device__ __forceinline__ float to_tf32(float x) {
    float r;
    asm("cvt.rna.tf32.f32 %0, %1;" : "=f"(r) : "f"(x));
    return r;
}

__device__ __forceinline__ void mma_tf32(float* d,
                                         const uint32_t* a,
                                         const uint32_t* b)
{
    asm volatile(
        "mma.sync.aligned.m16n8k8.row.col.f32.tf32.tf32.f32 "
        "{%0,%1,%2,%3}, {%4,%5,%6,%7}, {%8,%9}, {%0,%1,%2,%3};"
        : "+f"(d[0]), "+f"(d[1]), "+f"(d[2]), "+f"(d[3])
        : "r"(a[0]), "r"(a[1]), "r"(a[2]), "r"(a[3]),
          "r"(b[0]), "r"(b[1]));
}

// C = A(MxK,row) * B ; TRANSB: B is (N x K) row-major (i.e. C = A * B^T)
// FLAGS: write (val >= 0.8) bytes instead of floats
// NOTE (!TRANSB path): requires Nn % 4 == 0 and B rows 16B-aligned (Nn*4 % 16 == 0).
// Holds for k_Wh (Nn=1024) and k_out (Nn=64).
template<bool TRANSB, bool FLAGS>
__device__ __forceinline__ void gemm_mma(const float* __restrict__ A,
                                         const float* __restrict__ B,
                                         float* __restrict__ C,
                                         unsigned char* __restrict__ CF,
                                         int M, int Nn, int K)
{
    __shared__ float As[TBM][AS_STRIDE];
    __shared__ float Bs[TBK][BS_STRIDE];

    const int tid  = threadIdx.x;          // 256
    const int lane = tid & 31;
    const int warp = tid >> 5;             // 0..7
    const int wm   = warp >> 2;            // 0..1  -> 64 rows
    const int wn   = warp & 3;             // 0..3  -> 32 cols
    const int bm   = blockIdx.y * TBM;
    const int bn   = blockIdx.x * TBN;
    const int g    = lane >> 2;            // 0..7
    const int tg   = lane & 3;             // 0..3

    float acc[4][4][4];
    #pragma unroll
    for (int i = 0; i < 4; i++)
        #pragma unroll
        for (int j = 0; j < 4; j++)
            #pragma unroll
            for (int e = 0; e < 4; e++) acc[i][j][e] = 0.f;

    for (int k0 = 0; k0 < K; k0 += TBK) {
        // ---- load A tile: 128 x 32, scalar (A rows only 8B-aligned for F_IN=1386) ----
        #pragma unroll
        for (int l = 0; l < 16; l++) {
            int idx = l * 256 + tid;
            int r = idx >> 5, c = idx & 31;
            int gm = bm + r, gk = k0 + c;
            float v = (gm < M && gk < K) ? A[(long long)gm * K + gk] : 0.f;
            As[r][c] = to_tf32(v);
        }
        // ---- load B tile: 32 x 128 ----
        if (!TRANSB) {
            // float4 vectorized (Nn % 4 == 0 guaranteed by callers)
            #pragma unroll
            for (int l = 0; l < 4; l++) {
                int idx = l * 256 + tid;          // 0..1023 over [kk][n4]
                int kk = idx >> 5, n4 = idx & 31;
                int gk = k0 + kk, gn = bn + n4 * 4;
                float4 v = make_float4(0.f, 0.f, 0.f, 0.f);
                if (gk < K && gn < Nn)
                    v = *(const float4*)&B[(long long)gk * Nn + gn];
                Bs[kk][n4 * 4 + 0] = to_tf32(v.x);
                Bs[kk][n4 * 4 + 1] = to_tf32(v.y);
                Bs[kk][n4 * 4 + 2] = to_tf32(v.z);
                Bs[kk][n4 * 4 + 3] = to_tf32(v.w);
            }
        } else {
            #pragma unroll
            for (int l = 0; l < 16; l++) {
                int idx = l * 256 + tid;
                int n = idx >> 5, kk = idx & 31;   // coalesced over k
                int gk = k0 + kk, gn = bn + n;
                float v = (gk < K && gn < Nn) ? B[(long long)gn * K + gk] : 0.f;
                Bs[kk][n] = to_tf32(v);
            }
        }
        __syncthreads();

        #pragma unroll
        for (int ks = 0; ks < TBK; ks += 8) {
            uint32_t af[4][4];
            #pragma unroll
            for (int mf = 0; mf < 4; mf++) {
                int r0 = wm * 64 + mf * 16 + g;
                af[mf][0] = __float_as_uint(As[r0    ][ks + tg    ]);
                af[mf][1] = __float_as_uint(As[r0 + 8][ks + tg    ]);
                af[mf][2] = __float_as_uint(As[r0    ][ks + tg + 4]);
                af[mf][3] = __float_as_uint(As[r0 + 8][ks + tg + 4]);
            }
            uint32_t bf[4][2];
            #pragma unroll
            for (int nf = 0; nf < 4; nf++) {
                int cb = wn * 32 + nf * 8 + g;
                bf[nf][0] = __float_as_uint(Bs[ks + tg    ][cb]);
                bf[nf][1] = __float_as_uint(Bs[ks + tg + 4][cb]);
            }
            #pragma unroll
            for (int mf = 0; mf < 4; mf++)
                #pragma unroll
                for (int nf = 0; nf < 4; nf++)
                    mma_tf32(acc[mf][nf], af[mf], bf[nf]);
        }
        __syncthreads();
    }

    // ---- store ----
    #pragma unroll
    for (int mf = 0; mf < 4; mf++) {
        #pragma unroll
        for (int nf = 0; nf < 4; nf++) {
            int r0 = bm + wm * 64 + mf * 16 + g;
            int c0 = bn + wn * 32 + nf * 8 + 2 * tg;
            #pragma unroll
            for (int e = 0; e < 4; e++) {
                int rr = r0 + (e >> 1) * 8;
                int cc = c0 + (e & 1);
                if (rr < M && cc < Nn) {
                    if (FLAGS) CF[(long long)rr * Nn + cc] = (acc[mf][nf][e] >= 0.8f) ? 1 : 0;
                    else       C [(long long)rr * Nn + cc] = acc[mf][nf][e];
                }
            }
        }
    }
}

// ---------------- kernels ----------------

__global__ void k_normalize(const float* __restrict__ x)
{
    const int row = blockIdx.x;
    const int tid = threadIdx.x;
    __shared__ float red[256];
    const float* xr = x + (long long)row * F_IN;
    float s = 0.f;
    for (int c = tid; c < F_IN; c += 256) { float v = xr[c]; s += v * v; }
    red[tid] = s; __syncthreads();
    for (int off = 128; off > 0; off >>= 1) {
        if (tid < off) red[tid] += red[tid + off];
        __syncthreads();
    }
    __shared__ float s_norm;
    if (tid == 0) s_norm = fmaxf(sqrtf(red[0]), 1e-12f);
    __syncthreads();
    float inv = 1.f / s_norm;
    float* o = g_xn + (long long)row * F_IN;
    for (int c = tid; c < F_IN; c += 256) o[c] = xr[c] * inv;
}

__global__ void __launch_bounds__(256) k_sim()
{
    gemm_mma<true, true>(g_xn, g_xn, nullptr, g_flags, N_NODES, N_NODES, F_IN);
}

__global__ void k_build_nbr()
{
    int row = blockIdx.x * blockDim.x + threadIdx.x;
    if (row >= N_NODES) return;
    const unsigned char* fr = g_flags + (long long)row * N_NODES;
    int cnt = 0;
    for (int j8 = 0; j8 < N_NODES; j8 += 8) {
        unsigned long long w = *(const unsigned long long*)(fr + j8);
        if (w == 0ull) continue;
        #pragma unroll
        for (int b = 0; b < 8; b++) {
            if ((w >> (8 * b)) & 0xffull) {
                if (cnt < KMAX) g_nbr[row * KMAX + cnt] = j8 + b;
                cnt++;
            }
        }
    }
    g_cnt[row] = (cnt > KMAX) ? KMAX : cnt;
}

__global__ void __launch_bounds__(256) k_Wh(const float* __restrict__ x,
                                            const float* __restrict__ W_att)
{
    const float* B = W_att + (long long)blockIdx.z * F_IN * NHID;
    float* C = g_Wh + (long long)blockIdx.z * N_NODES * NHID;
    gemm_mma<false, false>(x, B, C, nullptr, N_NODES, NHID, F_IN);
}

__global__ void k_f12(const float* __restrict__ a_att)
{
    const int i = blockIdx.x, h = blockIdx.y, tid = threadIdx.x; // 128
    const float* w = g_Wh + ((long long)h * N_NODES + i) * NHID;
    const float* a = a_att + (long long)h * 2 * NHID;
    float s1 = 0.f, s2 = 0.f;
    for (int c = tid; c < NHID; c += 128) {
        float v = w[c];
        s1 = fmaf(v, a[c], s1);
        s2 = fmaf(v, a[NHID + c], s2);
    }
    __shared__ float r1[128], r2[128];
    r1[tid] = s1; r2[tid] = s2; __syncthreads();
    for (int off = 64; off > 0; off >>= 1) {
        if (tid < off) { r1[tid] += r1[tid + off]; r2[tid] += r2[tid + off]; }
        __syncthreads();
    }
    if (tid == 0) { g_f1[h * N_NODES + i] = r1[0]; g_f2[h * N_NODES + i] = r2[0]; }
}

__global__ void k_head_attn()
{
    const int i = blockIdx.x, h = blockIdx.y, tid = threadIdx.x; // 256
    __shared__ float w[KMAX];
    __shared__ int   nb[KMAX];
    __shared__ int   scnt;
    if (tid == 0) {
        int c = g_cnt[i]; scnt = c;
        float f1i = g_f1[h * N_NODES + i];
        float m = -INFINITY;
        for (int j = 0; j < c; j++) {
            int col = g_nbr[i * KMAX + j]; nb[j] = col;
            float v = f1i + g_f2[h * N_NODES + col];
            v = (v > 0.f) ? v : LRELU_A * v;
            w[j] = v; if (v > m) m = v;
        }
        float s = 0.f;
        for (int j = 0; j < c; j++) { float e = expf(w[j] - m); w[j] = e; s += e; }
        float inv = 1.f / s;
        for (int j = 0; j < c; j++) w[j] *= inv;
    }
    __syncthreads();
    const int c = scnt;
    for (int col = tid; col < NHID; col += 256) {
        float acc = 0.f;
        for (int j = 0; j < c; j++)
            acc = fmaf(w[j], g_Wh[((long long)h * N_NODES + nb[j]) * NHID + col], acc);
        acc = (acc > 0.f) ? acc : expm1f(acc);   // ELU
        g_hcat[(long long)i * (NHEADS * NHID) + h * NHID + col] = acc;
    }
}

__global__ void __launch_bounds__(256) k_out(const float* __restrict__ W_out)
{
    gemm_mma<false, false>(g_hcat, W_out, g_out1, nullptr, N_NODES, CODE, NHEADS * NHID);
}

__global__ void k_f12o(const float* __restrict__ a_out)
{
    const int i = blockIdx.x, tid = threadIdx.x; // 64
    float v = g_out1[i * CODE + tid];
    float s1 = v * a_out[tid];
    float s2 = v * a_out[CODE + tid];
    __shared__ float r1[64], r2[64];
    r1[tid] = s1; r2[tid] = s2; __syncthreads();
    for (int off = 32; off > 0; off >>= 1) {
        if (tid < off) { r1[tid] += r1[tid + off]; r2[tid] += r2[tid + off]; }
        __syncthreads();
    }
    if (tid == 0) { g_f1o[i] = r1[0]; g_f2o[i] = r2[0]; }
}

__global__ void k_final(float* __restrict__ out)
{
    const int i = blockIdx.x, tid = threadIdx.x; // 64
    __shared__ float w[KMAX];
    __shared__ int   nb[KMAX];
    __shared__ int   scnt;
    if (tid == 0) {
        int c = g_cnt[i]; scnt = c;
        float f1i = g_f1o[i];
        float m = -INFINITY;
        for (int j = 0; j < c; j++) {
            int col = g_nbr[i * KMAX + j]; nb[j] = col;
            float v = f1i + g_f2o[col];
            v = (v > 0.f) ? v : LRELU_A * v;
            w[j] = v; if (v > m) m = v;
        }
        float s = 0.f;
        for (int j = 0; j < c; j++) { float e = expf(w[j] - m); w[j] = e; s += e; }
        float inv = 1.f / s;
        for (int j = 0; j < c; j++) w[j] *= inv;
    }
    __syncthreads();
    const int c = scnt;
    float acc = 0.f;
    for (int j = 0; j < c; j++)
        acc = fmaf(w[j], g_out1[nb[j] * CODE + tid], acc);
    out[i * CODE + tid] = tanhf(acc);
}

// ---------------- launch ----------------
extern "C" void kernel_launch(void* const* d_in, const int* in_sizes, int n_in,
                              void* d_out, int out_size)
{
    const float* x     = (const float*)d_in[0];
    const float* W_att = (const float*)d_in[1];
    const float* a_att = (const float*)d_in[2];
    const float* W_out = (const float*)d_in[3];
    const float* a_out = (const float*)d_in[4];
    float* out = (float*)d_out;

    k_normalize<<<N_NODES, 256>>>(x);
    k_sim<<<dim3(N_NODES / TBN, N_NODES / TBM), 256>>>();
    k_build_nbr<<<N_NODES / 256, 256>>>();
    k_Wh<<<dim3(NHID / TBN, N_NODES / TBM, NHEADS), 256>>>(x, W_att);
    k_f12<<<dim3(N_NODES, NHEADS), 128>>>(a_att);
    k_head_attn<<<dim3(N_NODES, NHEADS), 256>>>();
    k_out<<<dim3(1, N_NODES / TBM), 256>>>(W_out);
    k_f12o<<<N_NODES, 64>>>(a_out);
    k_final<<<N_NODES, 64>>>(out);
}